// round 4
// baseline (speedup 1.0000x reference)
#include <cuda_runtime.h>
#include <cstdint>

// MC3DAD geometry features: per-point kNN (k=5) covariance-trace curvature.
// B=8, N=4096, D=3. One thread per point, whole batch resident in smem.

#define NPTS 4096
#define NBATCH 8
#define TPB 128

// Sentinel key: dist=+inf, index=0xFFFFFFFF. Top-32 bits are +inf float bits,
// NOT NaN (the ~0ULL sentinel previously poisoned the running threshold w).
#define SENT_KEY ((((unsigned long long)0x7f800000u) << 32) | 0xFFFFFFFFu)

// ---------------- packed f32x2 helpers (Blackwell) ----------------
__device__ __forceinline__ unsigned long long f32x2_mul(unsigned long long a, unsigned long long b) {
    unsigned long long r;
    asm("mul.rn.f32x2 %0, %1, %2;" : "=l"(r) : "l"(a), "l"(b));
    return r;
}
__device__ __forceinline__ unsigned long long f32x2_add(unsigned long long a, unsigned long long b) {
    unsigned long long r;
    asm("add.rn.f32x2 %0, %1, %2;" : "=l"(r) : "l"(a), "l"(b));
    return r;
}
__device__ __forceinline__ unsigned long long f32x2_fma(unsigned long long a, unsigned long long b, unsigned long long c) {
    unsigned long long r;
    asm("fma.rn.f32x2 %0, %1, %2, %3;" : "=l"(r) : "l"(a), "l"(b), "l"(c));
    return r;
}
__device__ __forceinline__ unsigned long long pk2(float lo, float hi) {
    unsigned long long r;
    asm("mov.b64 %0, {%1, %2};" : "=l"(r) : "f"(lo), "f"(hi));
    return r;
}
__device__ __forceinline__ void up2(unsigned long long v, float& lo, float& hi) {
    asm("mov.b64 {%0, %1}, %2;" : "=f"(lo), "=f"(hi) : "l"(v));
}

// Insert candidate with clamped-d2/index u64 key into sorted 5-list (k0<=..<=k4).
// Key ordering == (dist ascending, index ascending) == jax.lax.top_k stability.
#define INSERT(dval, jj)                                                            \
    do {                                                                            \
        float _dc = fmaxf((dval), 0.0f);                                            \
        unsigned long long _key =                                                   \
            ((unsigned long long)__float_as_uint(_dc) << 32) | (unsigned)(jj);      \
        if (_key < k4) {                                                            \
            k4 = _key;                                                              \
            if (k4 < k3) { unsigned long long _t = k3; k3 = k4; k4 = _t; }          \
            if (k3 < k2) { unsigned long long _t = k2; k2 = k3; k3 = _t; }          \
            if (k2 < k1) { unsigned long long _t = k1; k1 = k2; k2 = _t; }          \
            if (k1 < k0) { unsigned long long _t = k0; k0 = k1; k1 = _t; }          \
            w = __uint_as_float((unsigned)(k4 >> 32));                              \
        }                                                                           \
    } while (0)

__global__ __launch_bounds__(TPB) void geom_kernel(const float* __restrict__ pcd,
                                                   float* __restrict__ out) {
    // smem layout (paired for f32x2 candidate processing):
    //   Af[p*4 + {0,1}] = x of candidates 2p, 2p+1 ; Af[p*4 + {2,3}] = y pair
    //   Bf[p*4 + {0,1}] = z pair                   ; Bf[p*4 + {2,3}] = |p|^2 pair
    extern __shared__ float sm[];
    float* Af = sm;               // 2048 * 4 floats = 32KB
    float* Bf = sm + NPTS * 2;    // 32KB

    const int b = blockIdx.y;
    const float* __restrict__ P = pcd + (size_t)b * NPTS * 3;

    // Stage the batch's point cloud + unfused squared norms into smem.
    for (int j = threadIdx.x; j < NPTS; j += TPB) {
        float x = P[3 * j + 0];
        float y = P[3 * j + 1];
        float z = P[3 * j + 2];
        // sq computed UNFUSED (mul then adds) to mirror jnp.sum(pcd*pcd, -1)
        float sq = __fadd_rn(__fadd_rn(__fmul_rn(x, x), __fmul_rn(y, y)), __fmul_rn(z, z));
        int p = j >> 1, l = j & 1;
        Af[p * 4 + l]     = x;
        Af[p * 4 + 2 + l] = y;
        Bf[p * 4 + l]     = z;
        Bf[p * 4 + 2 + l] = sq;
    }
    __syncthreads();

    const int i = blockIdx.x * TPB + threadIdx.x;
    const float xi = P[3 * i + 0];
    const float yi = P[3 * i + 1];
    const float zi = P[3 * i + 2];
    const float sqi = __fadd_rn(__fadd_rn(__fmul_rn(xi, xi), __fmul_rn(yi, yi)),
                                __fmul_rn(zi, zi));

    const unsigned long long xi2 = pk2(xi, xi);
    const unsigned long long yi2 = pk2(yi, yi);
    const unsigned long long zi2 = pk2(zi, zi);
    const unsigned long long si2 = pk2(sqi, sqi);
    const unsigned long long n22 = pk2(-2.0f, -2.0f);

    unsigned long long k0 = SENT_KEY, k1 = SENT_KEY, k2 = SENT_KEY,
                       k3 = SENT_KEY, k4 = SENT_KEY;
    float w = __uint_as_float(0x7f800000u);  // +inf

    const ulonglong2* __restrict__ A8 = (const ulonglong2*)Af;
    const ulonglong2* __restrict__ B8 = (const ulonglong2*)Bf;

#pragma unroll 4
    for (int p = 0; p < NPTS / 2; ++p) {
        ulonglong2 av = A8[p];  // av.x = (x_{2p}, x_{2p+1}), av.y = y pair
        ulonglong2 cv = B8[p];  // cv.x = z pair, cv.y = sq pair
        // dot = fma(z,z, fma(y,y, x*x)) per lane (Eigen K=3 fma chain)
        unsigned long long m = f32x2_mul(xi2, av.x);
        m = f32x2_fma(yi2, av.y, m);
        m = f32x2_fma(zi2, cv.x, m);
        unsigned long long base = f32x2_add(si2, cv.y);     // sq_i + sq_j
        // d2 = base - 2*dot  (fma by -2 is bit-identical: *2 is exact)
        unsigned long long d2p = f32x2_fma(n22, m, base);
        float dlo, dhi;
        up2(d2p, dlo, dhi);
        float mn = fminf(dlo, dhi);
        if (mn < w) {
            int j = 2 * p;
            if (dlo < w) { INSERT(dlo, j); }
            if (dhi < w) { INSERT(dhi, j + 1); }
        }
    }

    // Epilogue: gather 5 neighbor coords, centroid, trace of covariance.
    unsigned idx[5] = {(unsigned)k0, (unsigned)k1, (unsigned)k2, (unsigned)k3, (unsigned)k4};
    float px[5], py[5], pz[5];
    float sx = 0.0f, sy = 0.0f, sz = 0.0f;
#pragma unroll
    for (int t = 0; t < 5; ++t) {
        unsigned j = idx[t] & (NPTS - 1);  // hard OOB guard (no-op when slots filled)
        int p = j >> 1, l = j & 1;
        float ax0 = Af[p * 4 + 0], ax1 = Af[p * 4 + 1];
        float ay0 = Af[p * 4 + 2], ay1 = Af[p * 4 + 3];
        float az0 = Bf[p * 4 + 0], az1 = Bf[p * 4 + 1];
        px[t] = l ? ax1 : ax0;
        py[t] = l ? ay1 : ay0;
        pz[t] = l ? az1 : az0;
        sx += px[t]; sy += py[t]; sz += pz[t];
    }
    float cx = sx / 5.0f, cy = sy / 5.0f, cz = sz / 5.0f;
    float tr = 0.0f;
#pragma unroll
    for (int t = 0; t < 5; ++t) {
        float dx = px[t] - cx, dy = py[t] - cy, dz = pz[t] - cz;
        tr += dx * dx + dy * dy + dz * dz;
    }
    out[b * NPTS + i] = tr * 0.25f;  // / (k - 1), exact scale
}

// Deterministic per-batch normalization: curvature = trace / (sum(trace) + 1e-8)
__global__ __launch_bounds__(512) void norm_kernel(float* __restrict__ out) {
    __shared__ float red[512];
    const int b = blockIdx.x;
    const int t = threadIdx.x;
    float v[NPTS / 512];
    float s = 0.0f;
#pragma unroll
    for (int q = 0; q < NPTS / 512; ++q) {
        v[q] = out[b * NPTS + q * 512 + t];
        s += v[q];
    }
    red[t] = s;
    __syncthreads();
#pragma unroll
    for (int o = 256; o > 0; o >>= 1) {
        if (t < o) red[t] += red[t + o];
        __syncthreads();
    }
    float denom = red[0] + 1e-8f;
#pragma unroll
    for (int q = 0; q < NPTS / 512; ++q) {
        out[b * NPTS + q * 512 + t] = v[q] / denom;
    }
}

extern "C" void kernel_launch(void* const* d_in, const int* in_sizes, int n_in,
                              void* d_out, int out_size) {
    const float* pcd = (const float*)d_in[0];  // [8, 4096, 3] f32; d_in[1] = k (compile-time 5)
    float* out = (float*)d_out;                // [8, 4096] f32

    cudaFuncSetAttribute(geom_kernel, cudaFuncAttributeMaxDynamicSharedMemorySize, 65536);

    dim3 grid(NPTS / TPB, NBATCH);  // (32, 8) = 256 blocks
    geom_kernel<<<grid, TPB, 65536>>>(pcd, out);
    norm_kernel<<<NBATCH, 512>>>(out);
}

// round 5
// speedup vs baseline: 1.0104x; 1.0104x over previous
#include <cuda_runtime.h>
#include <cstdint>

// MC3DAD geometry features: per-point kNN (k=5) covariance-trace curvature.
// B=8, N=4096, D=3. FOUR threads per point (candidate dim split 4-way, strided),
// whole batch resident in smem; partial top-5 lists merged via shfl.xor.

#define NPTS 4096
#define NBATCH 8
#define TPB 512
#define SPLIT 4
#define PPB (TPB / SPLIT)   // 128 points per block

// Sentinel key: dist=+inf, index=0xFFFFFFFF (top bits are +inf, NOT NaN).
#define SENT_KEY ((((unsigned long long)0x7f800000u) << 32) | 0xFFFFFFFFu)

// ---------------- packed f32x2 helpers (Blackwell) ----------------
__device__ __forceinline__ unsigned long long f32x2_mul(unsigned long long a, unsigned long long b) {
    unsigned long long r;
    asm("mul.rn.f32x2 %0, %1, %2;" : "=l"(r) : "l"(a), "l"(b));
    return r;
}
__device__ __forceinline__ unsigned long long f32x2_add(unsigned long long a, unsigned long long b) {
    unsigned long long r;
    asm("add.rn.f32x2 %0, %1, %2;" : "=l"(r) : "l"(a), "l"(b));
    return r;
}
__device__ __forceinline__ unsigned long long f32x2_fma(unsigned long long a, unsigned long long b, unsigned long long c) {
    unsigned long long r;
    asm("fma.rn.f32x2 %0, %1, %2, %3;" : "=l"(r) : "l"(a), "l"(b), "l"(c));
    return r;
}
__device__ __forceinline__ unsigned long long pk2(float lo, float hi) {
    unsigned long long r;
    asm("mov.b64 %0, {%1, %2};" : "=l"(r) : "f"(lo), "f"(hi));
    return r;
}
__device__ __forceinline__ void up2(unsigned long long v, float& lo, float& hi) {
    asm("mov.b64 {%0, %1}, %2;" : "=f"(lo), "=f"(hi) : "l"(v));
}

// Insert pre-built key into sorted 5-list (k0<=..<=k4), dropping largest.
#define INSERT_KEY(_keyv)                                                           \
    do {                                                                            \
        unsigned long long _key = (_keyv);                                          \
        if (_key < k4) {                                                            \
            k4 = _key;                                                              \
            if (k4 < k3) { unsigned long long _t = k3; k3 = k4; k4 = _t; }          \
            if (k3 < k2) { unsigned long long _t = k2; k2 = k3; k3 = _t; }          \
            if (k2 < k1) { unsigned long long _t = k1; k1 = k2; k2 = _t; }          \
            if (k1 < k0) { unsigned long long _t = k0; k0 = k1; k1 = _t; }          \
        }                                                                           \
    } while (0)

// Hot-loop insert: clamp d2, build key, insert, refresh threshold w.
#define INSERT(dval, jj)                                                            \
    do {                                                                            \
        float _dc = fmaxf((dval), 0.0f);                                            \
        INSERT_KEY(((unsigned long long)__float_as_uint(_dc) << 32) | (unsigned)(jj)); \
        w = __uint_as_float((unsigned)(k4 >> 32));                                  \
    } while (0)

__global__ __launch_bounds__(TPB, 2) void geom_kernel(const float* __restrict__ pcd,
                                                      float* __restrict__ out) {
    // smem layout (paired for f32x2 candidate processing):
    //   Af[p*4 + {0,1}] = x of candidates 2p, 2p+1 ; Af[p*4 + {2,3}] = y pair
    //   Bf[p*4 + {0,1}] = z pair                   ; Bf[p*4 + {2,3}] = |p|^2 pair
    extern __shared__ float sm[];
    float* Af = sm;               // 32KB
    float* Bf = sm + NPTS * 2;    // 32KB

    const int b = blockIdx.y;
    const float* __restrict__ P = pcd + (size_t)b * NPTS * 3;

    // Stage point cloud + unfused squared norms (mirrors jnp.sum(pcd*pcd, -1)).
    for (int j = threadIdx.x; j < NPTS; j += TPB) {
        float x = P[3 * j + 0];
        float y = P[3 * j + 1];
        float z = P[3 * j + 2];
        float sq = __fadd_rn(__fadd_rn(__fmul_rn(x, x), __fmul_rn(y, y)), __fmul_rn(z, z));
        int p = j >> 1, l = j & 1;
        Af[p * 4 + l]     = x;
        Af[p * 4 + 2 + l] = y;
        Bf[p * 4 + l]     = z;
        Bf[p * 4 + 2 + l] = sq;
    }
    __syncthreads();

    const int s = threadIdx.x & (SPLIT - 1);          // candidate-slice id 0..3
    const int pl = threadIdx.x >> 2;                  // point-local 0..127
    const int i = blockIdx.x * PPB + pl;              // global point in batch

    const float xi = P[3 * i + 0];
    const float yi = P[3 * i + 1];
    const float zi = P[3 * i + 2];
    const float sqi = __fadd_rn(__fadd_rn(__fmul_rn(xi, xi), __fmul_rn(yi, yi)),
                                __fmul_rn(zi, zi));

    const unsigned long long xi2 = pk2(xi, xi);
    const unsigned long long yi2 = pk2(yi, yi);
    const unsigned long long zi2 = pk2(zi, zi);
    const unsigned long long si2 = pk2(sqi, sqi);
    const unsigned long long n22 = pk2(-2.0f, -2.0f);

    unsigned long long k0 = SENT_KEY, k1 = SENT_KEY, k2 = SENT_KEY,
                       k3 = SENT_KEY, k4 = SENT_KEY;
    float w = __uint_as_float(0x7f800000u);  // +inf

    const ulonglong2* __restrict__ A8 = (const ulonglong2*)Af;
    const ulonglong2* __restrict__ B8 = (const ulonglong2*)Bf;

    // Strided slice: entry p = 4t + s (candidates 2p, 2p+1). The 4 lanes of a
    // point hit consecutive 16B smem lines -> conflict-free broadcast groups.
#pragma unroll 4
    for (int t = 0; t < NPTS / 2 / SPLIT; ++t) {
        const int p = (t << 2) + s;
        ulonglong2 av = A8[p];  // x pair, y pair
        ulonglong2 cv = B8[p];  // z pair, sq pair
        unsigned long long m = f32x2_mul(xi2, av.x);
        m = f32x2_fma(yi2, av.y, m);
        m = f32x2_fma(zi2, cv.x, m);
        unsigned long long base = f32x2_add(si2, cv.y);   // sq_i + sq_j
        unsigned long long d2p = f32x2_fma(n22, m, base); // base - 2*dot (exact)
        float dlo, dhi;
        up2(d2p, dlo, dhi);
        float mn = fminf(dlo, dhi);
        if (mn < w) {
            int j = 2 * p;
            if (dlo < w) { INSERT(dlo, j); }
            if (dhi < w) { INSERT(dhi, j + 1); }
        }
    }

    // Merge the 4 per-slice top-5 lists (exact: u64 keys are globally unique).
#pragma unroll
    for (int mask = 1; mask <= 2; mask <<= 1) {
        unsigned long long o0 = __shfl_xor_sync(0xFFFFFFFFu, k0, mask);
        unsigned long long o1 = __shfl_xor_sync(0xFFFFFFFFu, k1, mask);
        unsigned long long o2 = __shfl_xor_sync(0xFFFFFFFFu, k2, mask);
        unsigned long long o3 = __shfl_xor_sync(0xFFFFFFFFu, k3, mask);
        unsigned long long o4 = __shfl_xor_sync(0xFFFFFFFFu, k4, mask);
        INSERT_KEY(o0); INSERT_KEY(o1); INSERT_KEY(o2); INSERT_KEY(o3); INSERT_KEY(o4);
    }

    // Epilogue (one lane per point): gather 5 neighbors, centroid, cov trace.
    if (s == 0) {
        unsigned idx[5] = {(unsigned)k0, (unsigned)k1, (unsigned)k2,
                           (unsigned)k3, (unsigned)k4};
        float px[5], py[5], pz[5];
        float sx = 0.0f, sy = 0.0f, sz = 0.0f;
#pragma unroll
        for (int t = 0; t < 5; ++t) {
            unsigned j = idx[t] & (NPTS - 1);  // hard OOB guard
            int p = j >> 1, l = j & 1;
            float ax0 = Af[p * 4 + 0], ax1 = Af[p * 4 + 1];
            float ay0 = Af[p * 4 + 2], ay1 = Af[p * 4 + 3];
            float az0 = Bf[p * 4 + 0], az1 = Bf[p * 4 + 1];
            px[t] = l ? ax1 : ax0;
            py[t] = l ? ay1 : ay0;
            pz[t] = l ? az1 : az0;
            sx += px[t]; sy += py[t]; sz += pz[t];
        }
        float cx = sx / 5.0f, cy = sy / 5.0f, cz = sz / 5.0f;
        float tr = 0.0f;
#pragma unroll
        for (int t = 0; t < 5; ++t) {
            float dx = px[t] - cx, dy = py[t] - cy, dz = pz[t] - cz;
            tr += dx * dx + dy * dy + dz * dz;
        }
        out[b * NPTS + i] = tr * 0.25f;  // / (k - 1)
    }
}

// Deterministic per-batch normalization: curvature = trace / (sum(trace) + 1e-8)
__global__ __launch_bounds__(512) void norm_kernel(float* __restrict__ out) {
    __shared__ float red[512];
    const int b = blockIdx.x;
    const int t = threadIdx.x;
    float v[NPTS / 512];
    float s = 0.0f;
#pragma unroll
    for (int q = 0; q < NPTS / 512; ++q) {
        v[q] = out[b * NPTS + q * 512 + t];
        s += v[q];
    }
    red[t] = s;
    __syncthreads();
#pragma unroll
    for (int o = 256; o > 0; o >>= 1) {
        if (t < o) red[t] += red[t + o];
        __syncthreads();
    }
    float denom = red[0] + 1e-8f;
#pragma unroll
    for (int q = 0; q < NPTS / 512; ++q) {
        out[b * NPTS + q * 512 + t] = v[q] / denom;
    }
}

extern "C" void kernel_launch(void* const* d_in, const int* in_sizes, int n_in,
                              void* d_out, int out_size) {
    const float* pcd = (const float*)d_in[0];  // [8, 4096, 3] f32
    float* out = (float*)d_out;                // [8, 4096] f32

    cudaFuncSetAttribute(geom_kernel, cudaFuncAttributeMaxDynamicSharedMemorySize, 65536);

    dim3 grid(NPTS / PPB, NBATCH);  // (32, 8) = 256 blocks of 512 threads
    geom_kernel<<<grid, TPB, 65536>>>(pcd, out);
    norm_kernel<<<NBATCH, 512>>>(out);
}